// round 16
// baseline (speedup 1.0000x reference)
#include <cuda_runtime.h>
#include <cuda_fp16.h>
#include <math.h>

// QuantumPoolingLayer R16: pool unchanged (contiguous streams + half2 scratch).
// Sim collapsed to closed form: layer-2 gates on wires 1-3 and CNOT cascade #2
// preserve the wire-0 halves (exact drop); cascade #1 folds to pairing
// s[k]<->s[15-k]; the product state factors the invariants:
//   <Z0> = (|a|^2-|c|^2) d0 - 4 Re(a c z0) r1 r2 r3
// with d0,z0 from qubit0's 2-vector and r_q = 2Re(qv0 conj(qv1)).

#define NQ 4

__device__ half2 g_part[64 * 32 * 512];   // [b][rg][m] -> (ch0, ch1) partials

// K1: grid (rg=32, b=64), 512 threads, 2 blocks/SM.
// Block streams rows [rg*2, rg*2+2), all j, all m: 256 KB CONTIGUOUS.
__global__ void __launch_bounds__(512, 2)
pool_kernel(const float* __restrict__ in)
{
    const int rg = blockIdx.x;           // 2-row group, 0..31
    const int b  = blockIdx.y;
    const int tid = threadIdx.x;
    const int ml  = tid & 127;           // m float4 lane
    const int p   = tid >> 7;            // 0..3

    const float* tb = in
        + ((size_t)(b * 64 + rg * 2) * 64) * 512
        + (size_t)p * 512 + (ml << 2);

    float4 acc0 = {0.f,0.f,0.f,0.f};     // colhalf 0 (j < 32)
    float4 acc1 = {0.f,0.f,0.f,0.f};     // colhalf 1 (j >= 32)

#pragma unroll
    for (int il = 0; il < 2; il++) {
        const float* rbase = tb + (size_t)il * 64 * 512;
        {
            float4 v[8];
#pragma unroll
            for (int k = 0; k < 8; k++)
                v[k] = __ldcs(reinterpret_cast<const float4*>(rbase + (size_t)k * 2048));
#pragma unroll
            for (int k = 0; k < 8; k++) {
                acc0.x += v[k].x; acc0.y += v[k].y; acc0.z += v[k].z; acc0.w += v[k].w;
            }
        }
        {
            float4 v[8];
#pragma unroll
            for (int k = 0; k < 8; k++)
                v[k] = __ldcs(reinterpret_cast<const float4*>(rbase + (size_t)(k + 8) * 2048));
#pragma unroll
            for (int k = 0; k < 8; k++) {
                acc1.x += v[k].x; acc1.y += v[k].y; acc1.z += v[k].z; acc1.w += v[k].w;
            }
        }
    }

    __shared__ __align__(16) float part[4][2][512];    // [p][ch][m], 16 KB
    reinterpret_cast<float4*>(part[p][0])[ml] = acc0;
    reinterpret_cast<float4*>(part[p][1])[ml] = acc1;
    __syncthreads();

    {
        float s0 = part[0][0][tid] + part[1][0][tid] + part[2][0][tid] + part[3][0][tid];
        float s1 = part[0][1][tid] + part[1][1][tid] + part[2][1][tid] + part[3][1][tid];
        g_part[(size_t)(b * 32 + rg) * 512 + tid] = __floats2half2_rn(s0, s1);
    }
}

// K2: one thread per sample, 512 blocks x 64 threads. Warp shares widx.
// Only gates 0..4 are needed (layer-1 all, layer-2 wire 0).
__global__ void __launch_bounds__(64)
sim_kernel(const float* __restrict__ w, float* __restrict__ out)
{
    const int n    = blockIdx.x * 64 + threadIdx.x;  // sample = b*512 + m
    const int lane = threadIdx.x & 31;
    const int wrp  = threadIdx.x >> 5;
    const int b = n >> 9;
    const int m = n & 511;

    // --- scratch combine: 32 coalesced half2 loads, independent ---
    float quad[4] = {0.f, 0.f, 0.f, 0.f};
#pragma unroll
    for (int rg = 0; rg < 32; rg++) {
        float2 v = __half22float2(g_part[(size_t)(b * 32 + rg) * 512 + m]);
        const int rh = rg >> 4;
        quad[rh * 2 + 0] += v.x;
        quad[rh * 2 + 1] += v.y;
    }

    // --- warp-cooperative gate table, gates 0..4 (widx = n>>6 uniform) ---
    __shared__ float sc[2][5][3][2];     // [warp][gate][comp][sin,cos]
    __shared__ float gt[2][5][4];        // [warp][gate][A,B,C,D]
    const float* wp = w + (size_t)(n >> 6) * 24;
    if (lane < 15) {
        const int g = lane / 3, c = lane - g * 3;
        float phi = wp[g * 3 + 0], th = wp[g * 3 + 1], om = wp[g * 3 + 2];
        float arg = (c == 0) ? 0.5f * th
                  : (c == 1) ? 0.5f * (phi + om)
                             : 0.5f * (phi - om);
        float sn, cs; __sincosf(arg, &sn, &cs);
        sc[wrp][g][c][0] = sn; sc[wrp][g][c][1] = cs;
    }
    __syncwarp();
    if (lane < 5) {
        float stt = sc[wrp][lane][0][0], ctt = sc[wrp][lane][0][1];
        float sa  = sc[wrp][lane][1][0], ca  = sc[wrp][lane][1][1];
        float sb  = sc[wrp][lane][2][0], cb  = sc[wrp][lane][2][1];
        gt[wrp][lane][0] = ctt * ca;   // A
        gt[wrp][lane][1] = ctt * sa;   // B
        gt[wrp][lane][2] = stt * cb;   // C
        gt[wrp][lane][3] = stt * sb;   // D
    }
    __syncwarp();

    // --- per-qubit 2-vectors after RY(x*pi) then layer-1 Rot ---
    // qv0 = U00*cs + U01*sn, qv1 = U10*cs + U11*sn with
    // U00=(A,-B), U01=(-C,-D), U10=(C,-D), U11=(A,B).
    float d0 = 0.f, z0r = 0.f, z0i = 0.f, rprod = 1.f;
#pragma unroll
    for (int q = 0; q < NQ; q++) {
        float x = tanhf(quad[q] * (1.0f / 1024.0f));
        float sn, cs; __sincosf(x * 1.57079632679489662f, &sn, &cs);
        const float A = gt[wrp][q][0], B = gt[wrp][q][1];
        const float C = gt[wrp][q][2], D = gt[wrp][q][3];
        float v0x = fmaf(A, cs, -C * sn), v0y = fmaf(-B, cs, -D * sn);
        float v1x = fmaf(C, cs,  A * sn), v1y = fmaf(-D, cs,  B * sn);
        if (q == 0) {
            d0  = (v0x*v0x + v0y*v0y) - (v1x*v1x + v1y*v1y);
            // z0 = qv0 * conj(qv1)
            z0r = fmaf(v0x, v1x,  v0y * v1y);
            z0i = fmaf(v0y, v1x, -v0x * v1y);
        } else {
            rprod *= 2.0f * fmaf(v0x, v1x, v0y * v1y);   // r_q
        }
    }

    // --- layer-2 wire-0 gate (gate 4): a = A-iB, c = C-iD ---
    const float A4 = gt[wrp][4][0], B4 = gt[wrp][4][1];
    const float C4 = gt[wrp][4][2], D4 = gt[wrp][4][3];
    float e  = (A4*A4 + B4*B4) - (C4*C4 + D4*D4);   // |a|^2 - |c|^2
    float f1 = fmaf(A4, C4, -B4 * D4);              // Re(a*c)
    float f2 = fmaf(A4, D4,  B4 * C4);              // -Im(a*c) (a*c = f1 - i*f2)
    // Re(a*c*z0) = f1*z0r + f2*z0i
    out[n] = fmaf(e, d0, -4.0f * fmaf(f1, z0r, f2 * z0i) * rprod);
}

extern "C" void kernel_launch(void* const* d_in, const int* in_sizes, int n_in,
                              void* d_out, int out_size)
{
    const float* in = (const float*)d_in[0];
    const float* w  = (const float*)d_in[1];
    if (n_in >= 2 && in_sizes[0] < in_sizes[1]) {   // defensive: identify by size
        in = (const float*)d_in[1];
        w  = (const float*)d_in[0];
    }
    dim3 grid1(32, 64);
    pool_kernel<<<grid1, 512>>>(in);
    sim_kernel<<<512, 64>>>(w, (float*)d_out);
}